// round 14
// baseline (speedup 1.0000x reference)
#include <cuda_runtime.h>
#include <cuda_bf16.h>

// Gather3d: x [1, 128, 16, 128, 128] f32, active_indices [128, 2] i32 in [0,112)
// out [128, 128, 18, 16, 16] f32:
//   out[n, c, T, i, j] = (T < 2) ? 0 : x[0, c, T-2, idx_y[n]+i, idx_x[n]+j]
//
// R13: amortize per-CTA overhead. One CTA = one n x 4 channels (4096 CTAs).
//   - lane = (i, j) of the 16x16 block: warp LDG spans 2 input rows (good L1
//     wavefront economy); warp STG is 128 B contiguous.
//   - per channel: 16 fully-unrolled independent loads (MLP=16), then 16
//     streaming stores; idx + base-pointer math paid once per CTA.
//   - zero pad frames written as float4 (1 STG.128 per 128 threads/channel).
//   - grid: channel-group outer, n inner -> all 128 n-CTAs per plane group
//     co-resident; each 64 KB (c,t) input plane DRAM-fetched once, L2-reused.
//   - __stcs keeps the 302 MB write stream from evicting read planes.

#define CC    128
#define TIN   16
#define TT    18
#define HW    128
#define NN    128
#define BH    16
#define BW    16
#define CPB   4                 // channels per CTA
#define CHUNK (BH * BW)         // 256 floats per (n,c,T) frame

__global__ __launch_bounds__(256) void gather3d_kernel(
    const float* __restrict__ x,
    const int*   __restrict__ idx,
    float*       __restrict__ out)
{
    // blockIdx.x = cg * NN + n   (n inner for cross-n L2 reuse)
    int n  = blockIdx.x & (NN - 1);
    int cg = blockIdx.x >> 7;         // channel group 0..31
    int c0 = cg * CPB;

    int tid = threadIdx.x;
    int j = tid & (BW - 1);
    int i = tid >> 4;

    int iy = __ldg(&idx[2 * n]);
    int ix = __ldg(&idx[2 * n + 1]);

    const float* src = x + ((c0 * TIN) * HW + (iy + i)) * HW + (ix + j);
    float*       dst = out + ((n * CC + c0) * TT) * CHUNK;

    const float4 z4 = make_float4(0.f, 0.f, 0.f, 0.f);

#pragma unroll
    for (int cl = 0; cl < CPB; ++cl) {
        const float* s = src + cl * (TIN * HW * HW);
        float*       d = dst + cl * (TT * CHUNK);

        // T = 0,1 zero frames: 512 floats = 128 float4 -> threads 0..127
        if (tid < 128)
            __stcs(reinterpret_cast<float4*>(d) + tid, z4);

        // 16 independent loads in flight, then drain to streaming stores
        float v[TIN];
#pragma unroll
        for (int t = 0; t < TIN; ++t)
            v[t] = __ldg(s + t * (HW * HW));

        float* dT = d + 2 * CHUNK + i * BW + j;
#pragma unroll
        for (int t = 0; t < TIN; ++t)
            __stcs(dT + t * CHUNK, v[t]);
    }
}

extern "C" void kernel_launch(void* const* d_in, const int* in_sizes, int n_in,
                              void* d_out, int out_size) {
    const float* x   = (const float*)d_in[0];
    const int*   idx = (const int*)d_in[1];
    float*       out = (float*)d_out;

    gather3d_kernel<<<(CC / CPB) * NN, 256>>>(x, idx, out);  // 4096 CTAs
}

// round 15
// speedup vs baseline: 1.0424x; 1.0424x over previous
#include <cuda_runtime.h>
#include <cuda_bf16.h>
#include <cstdint>

// Gather3d: x [1, 128, 16, 128, 128] f32, active_indices [128, 2] i32 in [0,112)
// out [128, 128, 18, 16, 16] f32:
//   out[n, c, T, i, j] = (T < 2) ? 0 : x[0, c, T-2, idx_y[n]+i, idx_x[n]+j]
//
// R14: bulk-async (TMA) stores. Each (n,c) output chunk is a contiguous,
// 16B-aligned 18 KB region. Stage it in smem (scalar gather loads -> STS,
// zero pad frames included), then one cp.async.bulk.global.shared::cta per
// CTA writes all 18 KB as a single sequential burst:
//   - DRAM write stream becomes large sequential bursts (HBM page locality,
//     fewer read/write turnarounds) instead of scattered 128 B warp stores.
//   - 4608 scalar STGs/CTA -> 1 UBLKCP; store-side L1 wavefronts vanish.
//   - wait_group.read only pins smem until the async engine has read it;
//     the actual DRAM drain overlaps subsequent CTAs.
// Read side keeps R9's mapping: lane=(i,j), warp spans 2 input rows, n-inner
// grid so all 128 n-CTAs per (c) plane-set are co-resident (L2 reuse).

#define CC   128
#define TIN  16
#define TT   18
#define HW   128
#define NN   128
#define BH   16
#define BW   16
#define CHUNK (BH * BW)            // 256 floats per frame
#define OUT_FLOATS (TT * CHUNK)    // 4608 floats = 18 KB per (n,c)

__global__ __launch_bounds__(256) void gather3d_kernel(
    const float* __restrict__ x,
    const int*   __restrict__ idx,
    float*       __restrict__ out)
{
    __shared__ __align__(128) float buf[OUT_FLOATS];   // 18 KB

    // blockIdx.x = c * NN + n  (n inner for cross-n L2 reuse of (c,t) planes)
    int n = blockIdx.x & (NN - 1);
    int c = blockIdx.x >> 7;

    int tid = threadIdx.x;
    int j = tid & (BW - 1);
    int i = tid >> 4;

    int iy = __ldg(&idx[2 * n]);
    int ix = __ldg(&idx[2 * n + 1]);

    // zero pad frames T=0,1: 512 floats = 128 float4
    if (tid < 128)
        reinterpret_cast<float4*>(buf)[tid] = make_float4(0.f, 0.f, 0.f, 0.f);

    // gather 16 time frames: 16 independent loads in flight per thread
    const float* src = x + ((c * TIN) * HW + (iy + i)) * HW + (ix + j);
    float v[TIN];
#pragma unroll
    for (int t = 0; t < TIN; ++t)
        v[t] = __ldg(src + t * (HW * HW));

    // stage into smem (stride-1 across tid -> conflict-free)
#pragma unroll
    for (int t = 0; t < TIN; ++t)
        buf[(2 + t) * CHUNK + tid] = v[t];

    __syncthreads();
    asm volatile("fence.proxy.async.shared::cta;" ::: "memory");

    if (tid == 0) {
        uint32_t sbuf;
        asm("{ .reg .u64 a; cvta.to.shared.u64 a, %1; cvt.u32.u64 %0, a; }"
            : "=r"(sbuf) : "l"(buf));
        float* dst = out + (size_t)(n * CC + c) * OUT_FLOATS;  // 18 KB-aligned
        asm volatile(
            "cp.async.bulk.global.shared::cta.bulk_group [%0], [%1], %2;"
            :: "l"(dst), "r"(sbuf), "r"((int)(OUT_FLOATS * 4))
            : "memory");
        asm volatile("cp.async.bulk.commit_group;" ::: "memory");
        // only need the smem *read* to finish before CTA exit frees smem
        asm volatile("cp.async.bulk.wait_group.read 0;" ::: "memory");
    }
}

extern "C" void kernel_launch(void* const* d_in, const int* in_sizes, int n_in,
                              void* d_out, int out_size) {
    const float* x   = (const float*)d_in[0];
    const int*   idx = (const int*)d_in[1];
    float*       out = (float*)d_out;

    gather3d_kernel<<<CC * NN, 256>>>(x, idx, out);  // 16384 CTAs
}